// round 4
// baseline (speedup 1.0000x reference)
#include <cuda_runtime.h>
#include <cuda_bf16.h>
#include <cstdint>

// ============================================================================
// RBF-SVM head:  out[64,8] = exp(-g*(||x||^2 - 2 x@C^T + ||c||^2)) @ W^T + b
// R4: harness compiles for PTX target sm_100 (NOT sm_100a) -> tcgen05 is
// unavailable. Rebuilt the cross-term GEMM on baseline-ISA tensor cores:
// mma.sync.m16n8k16 bf16 + ldmatrix + cp.async. Still memory-bound by design:
// 131 MB of centers read once at ~32 FLOP/B.
// ============================================================================

#define GAMMA_F 1e-4f
static constexpr int BATCH  = 64;
static constexpr int NC     = 500;       // real centers
static constexpr int NCP    = 512;       // padded centers
static constexpr int KDIM   = 65536;
static constexpr int NSPLIT = 37;        // K splits (4 tiles * 37 = 148 CTAs = 1 wave)
static constexpr int NTILES = 4;         // center tiles of 128
static constexpr int MT     = 128;       // centers per CTA tile
static constexpr int KT     = 64;        // K elements per smem tile
static constexpr int NKT    = KDIM / KT; // 1024 k-tiles total

// ---- device scratch (no allocations allowed) ----
__device__ __nv_bfloat16 g_xb[BATCH * KDIM];       // 8 MB bf16 x
__device__ float g_xsq[BATCH];
__device__ float g_csqp[NSPLIT * NCP];             // per-split ||c||^2 partials
__device__ float g_partial[NSPLIT * NCP * BATCH];  // cross partials 4.85 MB
__device__ float g_outp[8 * 512];                  // epilogue block partials

// ============================================================================
// helpers
// ============================================================================
__device__ __forceinline__ uint32_t smem_u32(const void* p) {
    uint32_t a;
    asm("{ .reg .u64 t; cvta.to.shared.u64 t, %1; cvt.u32.u64 %0, t; }" : "=r"(a) : "l"(p));
    return a;
}

#define SMEM_SWIZZLE_128B(byte_offset) \
    ((byte_offset) ^ (((byte_offset) >> 3) & 0x70))

__device__ __forceinline__ void ldsm_x4(uint32_t* r, uint32_t addr) {
    asm volatile("ldmatrix.sync.aligned.m8n8.x4.shared.b16 {%0,%1,%2,%3}, [%4];"
                 : "=r"(r[0]), "=r"(r[1]), "=r"(r[2]), "=r"(r[3]) : "r"(addr));
}

__device__ __forceinline__ void mma16816(float* d, const uint32_t* a, const uint32_t* b) {
    asm volatile(
        "mma.sync.aligned.m16n8k16.row.col.f32.bf16.bf16.f32 "
        "{%0,%1,%2,%3}, {%4,%5,%6,%7}, {%8,%9}, {%0,%1,%2,%3};\n"
        : "+f"(d[0]), "+f"(d[1]), "+f"(d[2]), "+f"(d[3])
        : "r"(a[0]), "r"(a[1]), "r"(a[2]), "r"(a[3]), "r"(b[0]), "r"(b[1]));
}

__device__ __forceinline__ unsigned pack_bf16x2(float lo, float hi) {
    __nv_bfloat162 t = __floats2bfloat162_rn(lo, hi);
    return *reinterpret_cast<unsigned*>(&t);
}

// ============================================================================
// Kernel 1: x fp32 -> bf16, compute ||x||^2 exactly in fp32
// ============================================================================
__global__ __launch_bounds__(256, 1) void prep_kernel(const float* __restrict__ x) {
    const int b = blockIdx.x;
    const int tid = threadIdx.x;
    const float4* xr = reinterpret_cast<const float4*>(x + (size_t)b * KDIM);
    uint2* xo = reinterpret_cast<uint2*>(g_xb + (size_t)b * KDIM);
    float sq = 0.f;
    for (int i = tid; i < KDIM / 4; i += 256) {
        float4 v = xr[i];
        sq += v.x * v.x + v.y * v.y + v.z * v.z + v.w * v.w;
        uint2 o;
        o.x = pack_bf16x2(v.x, v.y);
        o.y = pack_bf16x2(v.z, v.w);
        xo[i] = o;
    }
    for (int off = 16; off > 0; off >>= 1) sq += __shfl_down_sync(0xffffffffu, sq, off);
    __shared__ float sm[8];
    if ((tid & 31) == 0) sm[tid >> 5] = sq;
    __syncthreads();
    if (tid == 0) {
        float t = 0.f;
        #pragma unroll
        for (int k = 0; k < 8; k++) t += sm[k];
        g_xsq[b] = t;
    }
}

// ============================================================================
// Kernel 2: split-K bf16 HMMA GEMM. grid = 4 tiles * 37 splits = 148 CTAs.
//   smA = centers tile [128 x 64] bf16 SW128 (converted from fp32 in regs)
//   smB = x tile       [64  x 64] bf16 SW128, double-buffered via cp.async
//   acc = per-warp 16x64 fp32 fragment accumulators (8 warps cover M=128)
// ============================================================================
__global__ __launch_bounds__(256, 1) void mma_kernel(const float* __restrict__ centers) {
    __shared__ __align__(1024) unsigned char smA[MT * 128];         // 16 KB
    __shared__ __align__(1024) unsigned char smB[2][BATCH * 128];   // 2 x 8 KB

    const int tid  = threadIdx.x;
    const int wid  = tid >> 5;
    const int lane = tid & 31;
    const int tile  = blockIdx.x & 3;
    const int split = blockIdx.x >> 2;
    const int t0 = split * NKT / NSPLIT;
    const int t1 = (split + 1) * NKT / NSPLIT;

    const uint32_t smA_u = smem_u32(smA);
    const uint32_t smB_u = smem_u32(smB);

    // ---- A global load mapping (fp32 centers -> regs) ----
    const int row_c = tid >> 4;           // + j*16
    const int col_c = tid & 15;           // *4 floats
    auto load_c = [&](int kt, float4* cr) {
        const size_t kb = (size_t)kt * KT;
        #pragma unroll
        for (int j = 0; j < 8; j++) {
            const int g = tile * MT + j * 16 + row_c;
            float4 v = make_float4(0.f, 0.f, 0.f, 0.f);
            if (g < NC) v = *reinterpret_cast<const float4*>(centers + (size_t)g * KDIM + kb + col_c * 4);
            cr[j] = v;
        }
    };

    // ---- B tile via cp.async (x already bf16 in g_xb) ----
    auto cpasync_b = [&](int kt, int buf) {
        #pragma unroll
        for (int j = 0; j < 2; j++) {
            const int c = tid * 2 + j;           // 512 chunks of 16B
            const int row = c >> 3, col = c & 7;
            const __nv_bfloat16* src = g_xb + (size_t)row * KDIM + (size_t)kt * KT + col * 8;
            const uint32_t off = (uint32_t)(row * 128 + col * 16);
            const uint32_t dst = smB_u + buf * 8192 + SMEM_SWIZZLE_128B(off);
            asm volatile("cp.async.ca.shared.global [%0], [%1], 16;" :: "r"(dst), "l"(src));
        }
        asm volatile("cp.async.commit_group;" ::: "memory");
    };

    // ---- ldmatrix lane addresses (SW128) ----
    const uint32_t a_row = (uint32_t)((wid * 16 + (lane & 15)) * 128 + ((lane >> 4) * 16));
    const uint32_t a_base = smA_u + SMEM_SWIZZLE_128B(a_row);
    const uint32_t b_rk  = (uint32_t)((lane & 7) + ((lane >> 4) & 1) * 8);
    const uint32_t b_k16 = (uint32_t)(((lane >> 3) & 1) * 16);
    uint32_t b_off[4];
    #pragma unroll
    for (int p = 0; p < 4; p++) {
        const uint32_t o = (p * 16 + b_rk) * 128 + b_k16;
        b_off[p] = SMEM_SWIZZLE_128B(o);
    }

    float acc[32];
    #pragma unroll
    for (int i = 0; i < 32; i++) acc[i] = 0.f;
    float csq[8];
    #pragma unroll
    for (int j = 0; j < 8; j++) csq[j] = 0.f;

    // ---- prologue ----
    float4 creg[8];
    cpasync_b(t0, 0);
    load_c(t0, creg);

    for (int it = t0; it < t1; ++it) {
        const int buf = (it - t0) & 1;
        const bool has_next = (it + 1 < t1);

        if (has_next) cpasync_b(it + 1, buf ^ 1);

        // convert + store centers tile (SW128), accumulate ||c||^2 in fp32
        #pragma unroll
        for (int j = 0; j < 8; j++) {
            const float4 v = creg[j];
            csq[j] += v.x * v.x + v.y * v.y + v.z * v.z + v.w * v.w;
            uint2 o;
            o.x = pack_bf16x2(v.x, v.y);
            o.y = pack_bf16x2(v.z, v.w);
            const uint32_t off = SMEM_SWIZZLE_128B((uint32_t)((j * 16 + row_c) * 128 + col_c * 8));
            *reinterpret_cast<uint2*>(smA + off) = o;
        }

        if (has_next) { asm volatile("cp.async.wait_group 1;" ::: "memory"); }
        else          { asm volatile("cp.async.wait_group 0;" ::: "memory"); }
        __syncthreads();

        if (has_next) load_c(it + 1, creg);   // LDGs in flight during compute

        // ---- compute: 4 k-steps of m16n8k16 over this tile ----
        const uint32_t bbase = smB_u + buf * 8192;
        #pragma unroll
        for (int ks = 0; ks < 4; ks++) {
            uint32_t a[4];
            ldsm_x4(a, a_base ^ (uint32_t)(ks * 32));
            #pragma unroll
            for (int p = 0; p < 4; p++) {
                uint32_t b[4];
                ldsm_x4(b, (bbase + b_off[p]) ^ (uint32_t)(ks * 32));
                mma16816(&acc[(p * 2 + 0) * 4], a, &b[0]);
                mma16816(&acc[(p * 2 + 1) * 4], a, &b[2]);
            }
        }
        __syncthreads();   // smA/smB[buf] consumed; safe to overwrite next iter
    }

    // ---- write ||c||^2 split partials (deterministic shfl tree) ----
    #pragma unroll
    for (int j = 0; j < 8; j++) {
        float v = csq[j];
        v += __shfl_down_sync(0xffffffffu, v, 8, 16);
        v += __shfl_down_sync(0xffffffffu, v, 4, 16);
        v += __shfl_down_sync(0xffffffffu, v, 2, 16);
        v += __shfl_down_sync(0xffffffffu, v, 1, 16);
        if ((tid & 15) == 0)
            g_csqp[split * NCP + tile * MT + j * 16 + (tid >> 4)] = v;
    }

    // ---- write cross partials: fragment (row g, col 2t) layout ----
    {
        const int g = lane >> 2;           // 0..7
        const int t2 = (lane & 3) * 2;     // batch col pair
        #pragma unroll
        for (int nblk = 0; nblk < 8; nblk++) {
            const float* d = &acc[nblk * 4];
            const int n0 = tile * MT + wid * 16 + g;
            const int b0 = nblk * 8 + t2;
            float2 v01 = make_float2(d[0], d[1]);
            float2 v23 = make_float2(d[2], d[3]);
            *reinterpret_cast<float2*>(g_partial + ((size_t)split * NCP + n0) * BATCH + b0) = v01;
            *reinterpret_cast<float2*>(g_partial + ((size_t)split * NCP + n0 + 8) * BATCH + b0) = v23;
        }
    }
}

// ============================================================================
// Kernel 3: reduce splits, rbf = exp(-g*dist), partial FC per block of 64 n
// ============================================================================
__global__ __launch_bounds__(256, 1) void epi_kernel(const float* __restrict__ fc_w) {
    __shared__ float s_w[8 * 64];
    __shared__ float s_csq[64];
    __shared__ float s_xsq[64];
    __shared__ float s_rbf[64 * 64];   // [nl][b]
    const int tid = threadIdx.x;
    const int nb = blockIdx.x * 64;

    if (tid < 64) {
        float c = 0.f;
        #pragma unroll
        for (int s = 0; s < NSPLIT; s++) c += g_csqp[s * NCP + nb + tid];
        s_csq[tid] = c;
        s_xsq[tid] = g_xsq[tid];
    }
    for (int i = tid; i < 512; i += 256) {
        const int h = i >> 6, nl = i & 63, n = nb + nl;
        s_w[i] = (n < NC) ? fc_w[h * NC + n] : 0.f;
    }
    __syncthreads();

    for (int p = tid; p < 64 * 64; p += 256) {
        const int nl = p >> 6, b = p & 63;
        float cr = 0.f;
        #pragma unroll
        for (int s = 0; s < NSPLIT; s++)
            cr += g_partial[((size_t)s * NCP + nb + nl) * BATCH + b];
        const float dist = s_xsq[b] - 2.f * cr + s_csq[nl];
        s_rbf[p] = __expf(-GAMMA_F * dist);
    }
    __syncthreads();

    // deterministic per-output reduction over this block's 64 centers
    for (int o = tid; o < 512; o += 256) {
        const int b = o >> 3, h = o & 7;
        float accv = 0.f;
        #pragma unroll
        for (int nl = 0; nl < 64; nl++) accv += s_rbf[nl * 64 + b] * s_w[h * 64 + nl];
        g_outp[blockIdx.x * 512 + o] = accv;
    }
}

// ============================================================================
// Kernel 4: sum 8 block partials + fc_b -> out[64,8]
// ============================================================================
__global__ void final_kernel(const float* __restrict__ fc_b, float* __restrict__ out) {
    const int o = threadIdx.x;  // 512
    float a = fc_b[o & 7];
    #pragma unroll
    for (int j = 0; j < 8; j++) a += g_outp[j * 512 + o];
    out[o] = a;
}

// ============================================================================
extern "C" void kernel_launch(void* const* d_in, const int* in_sizes, int n_in,
                              void* d_out, int out_size) {
    (void)in_sizes; (void)n_in; (void)out_size;
    const float* x       = (const float*)d_in[0];
    const float* centers = (const float*)d_in[1];
    const float* fc_w    = (const float*)d_in[2];
    const float* fc_b    = (const float*)d_in[3];
    float* out = (float*)d_out;

    prep_kernel<<<BATCH, 256>>>(x);
    mma_kernel<<<NTILES * NSPLIT, 256>>>(centers);
    epi_kernel<<<8, 256>>>(fc_w);
    final_kernel<<<1, 512>>>(fc_b, out);
}

// round 6
// speedup vs baseline: 1.5238x; 1.5238x over previous
#include <cuda_runtime.h>
#include <cuda_bf16.h>
#include <cstdint>

// ============================================================================
// RBF-SVM head:  out[64,8] = exp(-g*(||x||^2 - 2 x@C^T + ||c||^2)) @ W^T + b
// R6 == R5 resubmitted verbatim (R5 hit a container-level infra failure; its
// instruction mix is identical to the R4 kernel that passed at 69.6us).
//  - mma: 2 CTAs/SM (NSPLIT 74, grid 296, launch_bounds(256,2))
//  - prep: 4 blocks per batch row (256 CTAs), quarter x_sq partials
//  - epi: 64 blocks (8 center-blocks x 8 batch-chunks)
// ============================================================================

#define GAMMA_F 1e-4f
static constexpr int BATCH  = 64;
static constexpr int NC     = 500;       // real centers
static constexpr int NCP    = 512;       // padded centers
static constexpr int KDIM   = 65536;
static constexpr int NSPLIT = 74;        // K splits (4 tiles * 74 = 296 CTAs = 2/SM)
static constexpr int NTILES = 4;         // center tiles of 128
static constexpr int MT     = 128;       // centers per CTA tile
static constexpr int KT     = 64;        // K elements per smem tile
static constexpr int NKT    = KDIM / KT; // 1024 k-tiles total

// ---- device scratch (no allocations allowed) ----
__device__ __nv_bfloat16 g_xb[BATCH * KDIM];       // 8 MB bf16 x
__device__ float g_xsq4[BATCH * 4];                // quarter-row ||x||^2 partials
__device__ float g_csqp[NSPLIT * NCP];             // per-split ||c||^2 partials
__device__ float g_partial[NSPLIT * NCP * BATCH];  // cross partials 9.7 MB
__device__ float g_outp[64 * 64];                  // epi block partials

// ============================================================================
// helpers
// ============================================================================
__device__ __forceinline__ uint32_t smem_u32(const void* p) {
    uint32_t a;
    asm("{ .reg .u64 t; cvta.to.shared.u64 t, %1; cvt.u32.u64 %0, t; }" : "=r"(a) : "l"(p));
    return a;
}

#define SMEM_SWIZZLE_128B(byte_offset) \
    ((byte_offset) ^ (((byte_offset) >> 3) & 0x70))

__device__ __forceinline__ void ldsm_x4(uint32_t* r, uint32_t addr) {
    asm volatile("ldmatrix.sync.aligned.m8n8.x4.shared.b16 {%0,%1,%2,%3}, [%4];"
                 : "=r"(r[0]), "=r"(r[1]), "=r"(r[2]), "=r"(r[3]) : "r"(addr));
}

__device__ __forceinline__ void mma16816(float* d, const uint32_t* a, const uint32_t* b) {
    asm volatile(
        "mma.sync.aligned.m16n8k16.row.col.f32.bf16.bf16.f32 "
        "{%0,%1,%2,%3}, {%4,%5,%6,%7}, {%8,%9}, {%0,%1,%2,%3};\n"
        : "+f"(d[0]), "+f"(d[1]), "+f"(d[2]), "+f"(d[3])
        : "r"(a[0]), "r"(a[1]), "r"(a[2]), "r"(a[3]), "r"(b[0]), "r"(b[1]));
}

__device__ __forceinline__ unsigned pack_bf16x2(float lo, float hi) {
    __nv_bfloat162 t = __floats2bfloat162_rn(lo, hi);
    return *reinterpret_cast<unsigned*>(&t);
}

// ============================================================================
// Kernel 1: x fp32 -> bf16 + quarter-row ||x||^2 partials. grid = 256.
// ============================================================================
__global__ __launch_bounds__(256, 1) void prep_kernel(const float* __restrict__ x) {
    const int b = blockIdx.x >> 2;
    const int q = blockIdx.x & 3;
    const int tid = threadIdx.x;
    const size_t base = (size_t)b * KDIM + (size_t)q * (KDIM / 4);
    const float4* xr = reinterpret_cast<const float4*>(x + base);
    uint2* xo = reinterpret_cast<uint2*>(g_xb + base);
    float sq = 0.f;
    #pragma unroll 4
    for (int i = tid; i < KDIM / 16; i += 256) {
        float4 v = xr[i];
        sq += v.x * v.x + v.y * v.y + v.z * v.z + v.w * v.w;
        uint2 o;
        o.x = pack_bf16x2(v.x, v.y);
        o.y = pack_bf16x2(v.z, v.w);
        xo[i] = o;
    }
    for (int off = 16; off > 0; off >>= 1) sq += __shfl_down_sync(0xffffffffu, sq, off);
    __shared__ float sm[8];
    if ((tid & 31) == 0) sm[tid >> 5] = sq;
    __syncthreads();
    if (tid == 0) {
        float t = 0.f;
        #pragma unroll
        for (int k = 0; k < 8; k++) t += sm[k];
        g_xsq4[b * 4 + q] = t;
    }
}

// ============================================================================
// Kernel 2: split-K bf16 HMMA GEMM. grid = 4 tiles * 74 splits = 296 CTAs.
// ============================================================================
__global__ __launch_bounds__(256, 2) void mma_kernel(const float* __restrict__ centers) {
    __shared__ __align__(1024) unsigned char smA[MT * 128];         // 16 KB
    __shared__ __align__(1024) unsigned char smB[2][BATCH * 128];   // 2 x 8 KB

    const int tid  = threadIdx.x;
    const int wid  = tid >> 5;
    const int lane = tid & 31;
    const int tile  = blockIdx.x & 3;
    const int split = blockIdx.x >> 2;
    const int t0 = split * NKT / NSPLIT;
    const int t1 = (split + 1) * NKT / NSPLIT;

    const uint32_t smA_u = smem_u32(smA);
    const uint32_t smB_u = smem_u32(smB);

    // ---- A global load mapping (fp32 centers -> regs) ----
    const int row_c = tid >> 4;           // + j*16
    const int col_c = tid & 15;           // *4 floats
    auto load_c = [&](int kt, float4* cr) {
        const size_t kb = (size_t)kt * KT;
        #pragma unroll
        for (int j = 0; j < 8; j++) {
            const int g = tile * MT + j * 16 + row_c;
            float4 v = make_float4(0.f, 0.f, 0.f, 0.f);
            if (g < NC) v = *reinterpret_cast<const float4*>(centers + (size_t)g * KDIM + kb + col_c * 4);
            cr[j] = v;
        }
    };

    // ---- B tile via cp.async (x already bf16 in g_xb) ----
    auto cpasync_b = [&](int kt, int buf) {
        #pragma unroll
        for (int j = 0; j < 2; j++) {
            const int c = tid * 2 + j;           // 512 chunks of 16B
            const int row = c >> 3, col = c & 7;
            const __nv_bfloat16* src = g_xb + (size_t)row * KDIM + (size_t)kt * KT + col * 8;
            const uint32_t off = (uint32_t)(row * 128 + col * 16);
            const uint32_t dst = smB_u + buf * 8192 + SMEM_SWIZZLE_128B(off);
            asm volatile("cp.async.ca.shared.global [%0], [%1], 16;" :: "r"(dst), "l"(src));
        }
        asm volatile("cp.async.commit_group;" ::: "memory");
    };

    // ---- ldmatrix lane addresses (SW128) ----
    const uint32_t a_row = (uint32_t)((wid * 16 + (lane & 15)) * 128 + ((lane >> 4) * 16));
    const uint32_t a_base = smA_u + SMEM_SWIZZLE_128B(a_row);
    const uint32_t b_rk  = (uint32_t)((lane & 7) + ((lane >> 4) & 1) * 8);
    const uint32_t b_k16 = (uint32_t)(((lane >> 3) & 1) * 16);
    uint32_t b_off[4];
    #pragma unroll
    for (int p = 0; p < 4; p++) {
        const uint32_t o = (p * 16 + b_rk) * 128 + b_k16;
        b_off[p] = SMEM_SWIZZLE_128B(o);
    }

    float acc[32];
    #pragma unroll
    for (int i = 0; i < 32; i++) acc[i] = 0.f;
    float csq[8];
    #pragma unroll
    for (int j = 0; j < 8; j++) csq[j] = 0.f;

    // ---- prologue ----
    float4 creg[8];
    cpasync_b(t0, 0);
    load_c(t0, creg);

    for (int it = t0; it < t1; ++it) {
        const int buf = (it - t0) & 1;
        const bool has_next = (it + 1 < t1);

        if (has_next) cpasync_b(it + 1, buf ^ 1);

        // convert + store centers tile (SW128), accumulate ||c||^2 in fp32
        #pragma unroll
        for (int j = 0; j < 8; j++) {
            const float4 v = creg[j];
            csq[j] += v.x * v.x + v.y * v.y + v.z * v.z + v.w * v.w;
            uint2 o;
            o.x = pack_bf16x2(v.x, v.y);
            o.y = pack_bf16x2(v.z, v.w);
            const uint32_t off = SMEM_SWIZZLE_128B((uint32_t)((j * 16 + row_c) * 128 + col_c * 8));
            *reinterpret_cast<uint2*>(smA + off) = o;
        }

        if (has_next) { asm volatile("cp.async.wait_group 1;" ::: "memory"); }
        else          { asm volatile("cp.async.wait_group 0;" ::: "memory"); }
        __syncthreads();

        if (has_next) load_c(it + 1, creg);   // LDGs in flight during compute

        // ---- compute: 4 k-steps of m16n8k16 over this tile ----
        const uint32_t bbase = smB_u + buf * 8192;
        #pragma unroll
        for (int ks = 0; ks < 4; ks++) {
            uint32_t a[4];
            ldsm_x4(a, a_base ^ (uint32_t)(ks * 32));
            #pragma unroll
            for (int p = 0; p < 4; p++) {
                uint32_t b[4];
                ldsm_x4(b, (bbase + b_off[p]) ^ (uint32_t)(ks * 32));
                mma16816(&acc[(p * 2 + 0) * 4], a, &b[0]);
                mma16816(&acc[(p * 2 + 1) * 4], a, &b[2]);
            }
        }
        __syncthreads();   // smA/smB[buf] consumed; safe to overwrite next iter
    }

    // ---- write ||c||^2 split partials (deterministic shfl tree) ----
    #pragma unroll
    for (int j = 0; j < 8; j++) {
        float v = csq[j];
        v += __shfl_down_sync(0xffffffffu, v, 8, 16);
        v += __shfl_down_sync(0xffffffffu, v, 4, 16);
        v += __shfl_down_sync(0xffffffffu, v, 2, 16);
        v += __shfl_down_sync(0xffffffffu, v, 1, 16);
        if ((tid & 15) == 0)
            g_csqp[split * NCP + tile * MT + j * 16 + (tid >> 4)] = v;
    }

    // ---- write cross partials: fragment (row g, col 2t) layout ----
    {
        const int g = lane >> 2;           // 0..7
        const int t2 = (lane & 3) * 2;     // batch col pair
        #pragma unroll
        for (int nblk = 0; nblk < 8; nblk++) {
            const float* d = &acc[nblk * 4];
            const int n0 = tile * MT + wid * 16 + g;
            const int b0 = nblk * 8 + t2;
            float2 v01 = make_float2(d[0], d[1]);
            float2 v23 = make_float2(d[2], d[3]);
            *reinterpret_cast<float2*>(g_partial + ((size_t)split * NCP + n0) * BATCH + b0) = v01;
            *reinterpret_cast<float2*>(g_partial + ((size_t)split * NCP + n0 + 8) * BATCH + b0) = v23;
        }
    }
}

// ============================================================================
// Kernel 3: reduce splits + rbf + partial FC. grid = 64 blocks:
//   nb = blockIdx.x & 7  (center block of 64), bc = blockIdx.x >> 3 (8 batches)
// ============================================================================
__global__ __launch_bounds__(256, 1) void epi_kernel(const float* __restrict__ fc_w) {
    __shared__ float s_w[8 * 64];      // [h][nl]
    __shared__ float s_csq[64];
    __shared__ float s_xsq[8];
    __shared__ float s_rbf[64 * 8];    // [nl][b8]
    const int tid = threadIdx.x;
    const int nb = (blockIdx.x & 7) * 64;
    const int bc = blockIdx.x >> 3;

    if (tid < 64) {
        float c = 0.f;
        for (int s = 0; s < NSPLIT; s++) c += g_csqp[s * NCP + nb + tid];
        s_csq[tid] = c;
    }
    if (tid >= 64 && tid < 72) {
        const int b = bc * 8 + (tid - 64);
        s_xsq[tid - 64] = g_xsq4[b * 4] + g_xsq4[b * 4 + 1] + g_xsq4[b * 4 + 2] + g_xsq4[b * 4 + 3];
    }
    for (int i = tid; i < 512; i += 256) {
        const int h = i >> 6, nl = i & 63, n = nb + nl;
        s_w[i] = (n < NC) ? fc_w[h * NC + n] : 0.f;
    }
    __syncthreads();

    #pragma unroll
    for (int p = tid; p < 512; p += 256) {
        const int nl = p >> 3, b8 = p & 7;
        float cr = 0.f;
        for (int s = 0; s < NSPLIT; s++)
            cr += g_partial[((size_t)s * NCP + nb + nl) * BATCH + bc * 8 + b8];
        const float dist = s_xsq[b8] - 2.f * cr + s_csq[nl];
        s_rbf[p] = __expf(-GAMMA_F * dist);
    }
    __syncthreads();

    if (tid < 64) {
        const int b8 = tid >> 3, h = tid & 7;
        float accv = 0.f;
        #pragma unroll
        for (int nl = 0; nl < 64; nl++) accv += s_rbf[nl * 8 + b8] * s_w[h * 64 + nl];
        g_outp[blockIdx.x * 64 + tid] = accv;
    }
}

// ============================================================================
// Kernel 4: sum 8 center-block partials + fc_b -> out[64,8]
// ============================================================================
__global__ void final_kernel(const float* __restrict__ fc_b, float* __restrict__ out) {
    const int o = threadIdx.x;          // 512: b = o>>3, h = o&7
    const int b = o >> 3, h = o & 7;
    const int bc = b >> 3, b8 = b & 7;
    float a = fc_b[h];
    #pragma unroll
    for (int nbk = 0; nbk < 8; nbk++)
        a += g_outp[(bc * 8 + nbk) * 64 + b8 * 8 + h];
    out[o] = a;
}

// ============================================================================
extern "C" void kernel_launch(void* const* d_in, const int* in_sizes, int n_in,
                              void* d_out, int out_size) {
    (void)in_sizes; (void)n_in; (void)out_size;
    const float* x       = (const float*)d_in[0];
    const float* centers = (const float*)d_in[1];
    const float* fc_w    = (const float*)d_in[2];
    const float* fc_b    = (const float*)d_in[3];
    float* out = (float*)d_out;

    prep_kernel<<<BATCH * 4, 256>>>(x);
    mma_kernel<<<NTILES * NSPLIT, 256>>>(centers);
    epi_kernel<<<64, 256>>>(fc_w);
    final_kernel<<<1, 512>>>(fc_b, out);
}